// round 6
// baseline (speedup 1.0000x reference)
#include <cuda_runtime.h>
#include <cuda_bf16.h>
#include <cstdint>
#include <math.h>

// Problem constants
#define BB   2
#define LL   4096
#define EE   512
#define HH   8
#define DD   64
#define WIN  128
#define NTOK (BB*LL)          // 8192
#define QKVN (3*EE)           // 1536

// ---------------------------------------------------------------------------
// Device scratch
// ---------------------------------------------------------------------------
__device__ float g_Q[BB*HH*LL*DD];
__device__ float g_K[BB*HH*LL*DD];
__device__ float g_V[BB*HH*LL*DD];
__device__ float g_O[BB*LL*EE];

// ---------------------------------------------------------------------------
// Helpers
// ---------------------------------------------------------------------------
__device__ __forceinline__ uint32_t f2tf32(float x) {
    uint32_t r;
    asm("cvt.rna.tf32.f32 %0, %1;" : "=r"(r) : "f"(x));
    return r;
}
__device__ __forceinline__ void split_tf32(float x, uint32_t& hi, uint32_t& lo) {
    uint32_t h = f2tf32(x);
    hi = h;
    lo = f2tf32(x - __uint_as_float(h));
}

__device__ __forceinline__ void mma_tf32(float* d, const uint32_t* a,
                                         const uint32_t* b) {
    asm volatile(
        "mma.sync.aligned.m16n8k8.row.col.f32.tf32.tf32.f32 "
        "{%0,%1,%2,%3}, {%4,%5,%6,%7}, {%8,%9}, {%0,%1,%2,%3};"
        : "+f"(d[0]), "+f"(d[1]), "+f"(d[2]), "+f"(d[3])
        : "r"(a[0]), "r"(a[1]), "r"(a[2]), "r"(a[3]),
          "r"(b[0]), "r"(b[1]));
}

__device__ __forceinline__ uint32_t smem_u32(const void* p) {
    uint32_t a;
    asm("{ .reg .u64 t; cvta.to.shared.u64 t, %1; cvt.u32.u64 %0, t; }"
        : "=r"(a) : "l"(p));
    return a;
}
__device__ __forceinline__ void cp16(uint32_t dst, const void* src) {
    asm volatile("cp.async.ca.shared.global [%0], [%1], 16;"
                 :: "r"(dst), "l"(src));
}
#define CP_COMMIT() asm volatile("cp.async.commit_group;" ::: "memory")

// ---------------------------------------------------------------------------
// tf32 mma.sync GEMM with cp.async double-buffered pipeline.
//   C[M,N] = A[M,K] @ Bw[N,K]^T + bias, K = 512.
//   CTA tile 128x128, BK=32, 8 warps, warp tile 64x32.
//   Raw f32 staged async; tf32 cvt happens inline on fragment loads.
// ---------------------------------------------------------------------------
#define SPAD 36
#define GSZ  (128 * SPAD)            // floats per plane
#define GEMM_SMEM (4 * GSZ * 4)      // A0 A1 B0 B1

__global__ __launch_bounds__(256) void tf32_gemm(
    const float* __restrict__ Ain, const float* __restrict__ Bw,
    const float* __restrict__ bias, float* __restrict__ outp, int mode)
{
    extern __shared__ float smg[];
    const uint32_t sbase = smem_u32(smg);

    const int tid = threadIdx.x;
    const int m0 = blockIdx.y * 128;
    const int n0 = blockIdx.x * 128;
    const float* A = (mode == 1) ? g_O : Ain;

    const int w    = tid >> 5;
    const int lane = tid & 31;
    const int g    = lane >> 2;
    const int c    = lane & 3;
    const int rm   = (w >> 2) * 64;
    const int cn   = (w & 3) * 32;

    float acc[4][4][4];
    #pragma unroll
    for (int mi = 0; mi < 4; mi++)
        #pragma unroll
        for (int ni = 0; ni < 4; ni++)
            #pragma unroll
            for (int r = 0; r < 4; r++) acc[mi][ni][r] = 0.f;

    const int lrow = tid >> 3;           // 0..31
    const int lk4  = (tid & 7) * 4;      // 0..28

    auto issue_chunk = [&](int kc, int p) {
        const float* Ag = A  + (size_t)m0 * EE + kc * 32;
        const float* Bg = Bw + (size_t)n0 * EE + kc * 32;
        #pragma unroll
        for (int i = 0; i < 4; i++) {
            int row = lrow + i * 32;
            cp16(sbase + (uint32_t)((p * GSZ + row * SPAD + lk4) * 4),
                 Ag + (size_t)row * EE + lk4);
            cp16(sbase + (uint32_t)(((2 + p) * GSZ + row * SPAD + lk4) * 4),
                 Bg + (size_t)row * EE + lk4);
        }
    };

    issue_chunk(0, 0);
    CP_COMMIT();

    for (int kc = 0; kc < 16; kc++) {
        const int p = kc & 1;
        if (kc < 15) {
            issue_chunk(kc + 1, p ^ 1);
            CP_COMMIT();
            asm volatile("cp.async.wait_group 1;" ::: "memory");
        } else {
            asm volatile("cp.async.wait_group 0;" ::: "memory");
        }
        __syncthreads();

        const float* Asp = smg + p * GSZ;
        const float* Bsp = smg + (2 + p) * GSZ;

        #pragma unroll
        for (int ks = 0; ks < 4; ks++) {
            uint32_t af[4][4], bf[4][2];
            #pragma unroll
            for (int mi = 0; mi < 4; mi++) {
                const float* base = Asp + (rm + mi * 16 + g) * SPAD + ks * 8;
                af[mi][0] = f2tf32(base[c]);
                af[mi][1] = f2tf32(base[8 * SPAD + c]);
                af[mi][2] = f2tf32(base[c + 4]);
                af[mi][3] = f2tf32(base[8 * SPAD + c + 4]);
            }
            #pragma unroll
            for (int ni = 0; ni < 4; ni++) {
                const float* base = Bsp + (cn + ni * 8 + g) * SPAD + ks * 8;
                bf[ni][0] = f2tf32(base[c]);
                bf[ni][1] = f2tf32(base[c + 4]);
            }
            #pragma unroll
            for (int mi = 0; mi < 4; mi++)
                #pragma unroll
                for (int ni = 0; ni < 4; ni++)
                    mma_tf32(acc[mi][ni], af[mi], bf[ni]);
        }
        __syncthreads();
    }

    // ---- epilogue ----
    float bv[4][2];
    #pragma unroll
    for (int ni = 0; ni < 4; ni++) {
        int gn = n0 + cn + ni * 8 + 2 * c;
        bv[ni][0] = bias[gn];
        bv[ni][1] = bias[gn + 1];
    }

    if (mode == 0) {
        const int gnb = n0 + cn;
        const int sel = gnb >> 9;
        const int h   = (gnb >> 6) & 7;
        const float scale = (sel == 0) ? 0.125f : 1.0f;
        float* dst = (sel == 0) ? g_Q : (sel == 1) ? g_K : g_V;
        #pragma unroll
        for (int mi = 0; mi < 4; mi++) {
            #pragma unroll
            for (int half = 0; half < 2; half++) {
                int gm  = m0 + rm + mi * 16 + g + half * 8;
                int bat = gm >> 12;
                int l   = gm & (LL - 1);
                size_t rowbase = (((size_t)(bat * HH + h) * LL) + l) * DD;
                #pragma unroll
                for (int ni = 0; ni < 4; ni++) {
                    int gn = n0 + cn + ni * 8 + 2 * c;
                    int d  = gn & 63;
                    float2 o;
                    o.x = (acc[mi][ni][half * 2 + 0] + bv[ni][0]) * scale;
                    o.y = (acc[mi][ni][half * 2 + 1] + bv[ni][1]) * scale;
                    *reinterpret_cast<float2*>(dst + rowbase + d) = o;
                }
            }
        }
    } else {
        #pragma unroll
        for (int mi = 0; mi < 4; mi++) {
            #pragma unroll
            for (int half = 0; half < 2; half++) {
                int gm = m0 + rm + mi * 16 + g + half * 8;
                #pragma unroll
                for (int ni = 0; ni < 4; ni++) {
                    int gn = n0 + cn + ni * 8 + 2 * c;
                    float2 o;
                    o.x = acc[mi][ni][half * 2 + 0] + bv[ni][0];
                    o.y = acc[mi][ni][half * 2 + 1] + bv[ni][1];
                    *reinterpret_cast<float2*>(outp + (size_t)gm * EE + gn) = o;
                }
            }
        }
    }
}

// ---------------------------------------------------------------------------
// Banded flash attention, split-tf32 MMA with pre-split K/V smem planes.
//   Planes: Qs (f32) | Kh | Kl | Vth | Vtl (transposed, d-major) | Ps (f32)
//   All score/PV fragment loads are bank-conflict-free (addr ≡ 4g+c mod 32).
// ---------------------------------------------------------------------------
#define APAD 68
#define PL   (64 * APAD)
#define ATTN_SMEM (6 * PL * 4)

__global__ __launch_bounds__(128) void attn_mma()
{
    extern __shared__ float sm[];
    float* Qs  = sm;
    float* Kh  = sm + 1 * PL;
    float* Kl  = sm + 2 * PL;
    float* Vth = sm + 3 * PL;
    float* Vtl = sm + 4 * PL;
    float* Ps  = sm + 5 * PL;

    const int q0 = blockIdx.x * 64;
    const int h  = blockIdx.y;
    const int b  = blockIdx.z;
    const int tid  = threadIdx.x;
    const int w    = tid >> 5;
    const int lane = tid & 31;
    const int g    = lane >> 2;
    const int c    = lane & 3;

    const size_t head_off = ((size_t)(b * HH + h) * LL) * DD;
    const float* Qg = g_Q + head_off;
    const float* Kg = g_K + head_off;
    const float* Vg = g_V + head_off;

    // Load Q tile [64][64] (plain f32; split per-warp inline later)
    #pragma unroll
    for (int i = 0; i < 8; i++) {
        int u = tid + i * 128;
        int row = u >> 4;
        int col = (u & 15) * 4;
        float4 v = *reinterpret_cast<const float4*>(&Qg[(size_t)(q0 + row) * DD + col]);
        *reinterpret_cast<float4*>(&Qs[row * APAD + col]) = v;
    }

    float om[2] = {-1e30f, -1e30f};
    float ol[2] = {0.f, 0.f};
    float oacc[8][4];
    #pragma unroll
    for (int nt = 0; nt < 8; nt++)
        #pragma unroll
        for (int r = 0; r < 4; r++) oacc[nt][r] = 0.f;

    __syncthreads();

    const int row_lo = 16 * w + g;
    const int q_lo = q0 + row_lo;
    const int q_hi = q_lo + 8;

    for (int ch = 0; ch < 5; ch++) {
        const int kcc = q0 - 128 + ch * 64;
        if (kcc + 64 <= 0 || kcc >= LL) continue;

        // ---- stage K (hi/lo) and V (transposed hi/lo) ----
        #pragma unroll
        for (int i = 0; i < 8; i++) {
            int u = tid + i * 128;
            int key_l = (u & 7) | ((u >> 7) << 3);   // 0..63
            int col   = ((u >> 3) & 15) << 2;        // 0..60
            int key = kcc + key_l;
            int kk = min(max(key, 0), LL - 1);

            float4 kv = *reinterpret_cast<const float4*>(&Kg[(size_t)kk * DD + col]);
            uint32_t hx, lx, hy, ly, hz, lz, hw, lw;
            split_tf32(kv.x, hx, lx); split_tf32(kv.y, hy, ly);
            split_tf32(kv.z, hz, lz); split_tf32(kv.w, hw, lw);
            float4 khv = make_float4(__uint_as_float(hx), __uint_as_float(hy),
                                     __uint_as_float(hz), __uint_as_float(hw));
            float4 klv = make_float4(__uint_as_float(lx), __uint_as_float(ly),
                                     __uint_as_float(lz), __uint_as_float(lw));
            *reinterpret_cast<float4*>(&Kh[key_l * APAD + col]) = khv;
            *reinterpret_cast<float4*>(&Kl[key_l * APAD + col]) = klv;

            float4 vv = *reinterpret_cast<const float4*>(&Vg[(size_t)kk * DD + col]);
            uint32_t vh[4], vl[4];
            split_tf32(vv.x, vh[0], vl[0]); split_tf32(vv.y, vh[1], vl[1]);
            split_tf32(vv.z, vh[2], vl[2]); split_tf32(vv.w, vh[3], vl[3]);
            #pragma unroll
            for (int j = 0; j < 4; j++) {
                Vth[(col + j) * APAD + key_l] = __uint_as_float(vh[j]);
                Vtl[(col + j) * APAD + key_l] = __uint_as_float(vl[j]);
            }
        }
        __syncthreads();

        // ---- scores S[16][64] per warp (3xTF32) ----
        float sacc[8][4];
        #pragma unroll
        for (int nt = 0; nt < 8; nt++)
            #pragma unroll
            for (int r = 0; r < 4; r++) sacc[nt][r] = 0.f;

        #pragma unroll
        for (int ks = 0; ks < 8; ks++) {
            const float* ab = Qs + row_lo * APAD + ks * 8;
            uint32_t ah[4], al[4];
            split_tf32(ab[c],                ah[0], al[0]);
            split_tf32(ab[8 * APAD + c],     ah[1], al[1]);
            split_tf32(ab[c + 4],            ah[2], al[2]);
            split_tf32(ab[8 * APAD + c + 4], ah[3], al[3]);
            #pragma unroll
            for (int nt = 0; nt < 8; nt++) {
                const int bidx = (nt * 8 + g) * APAD + ks * 8;
                uint32_t bh[2], bl[2];
                bh[0] = __float_as_uint(Kh[bidx + c]);
                bh[1] = __float_as_uint(Kh[bidx + c + 4]);
                bl[0] = __float_as_uint(Kl[bidx + c]);
                bl[1] = __float_as_uint(Kl[bidx + c + 4]);
                mma_tf32(sacc[nt], ah, bh);
                mma_tf32(sacc[nt], al, bh);
                mma_tf32(sacc[nt], ah, bl);
            }
        }

        // ---- mask ----
        #pragma unroll
        for (int nt = 0; nt < 8; nt++) {
            #pragma unroll
            for (int r = 0; r < 4; r++) {
                int key = kcc + nt * 8 + 2 * c + (r & 1);
                int q   = (r >> 1) ? q_hi : q_lo;
                int dlt = q - key;
                bool ok = (key >= 0) && (key < LL) && (dlt != 0) &&
                          (dlt <= WIN) && (dlt >= -WIN);
                if (!ok) sacc[nt][r] = -1e30f;
            }
        }

        // ---- online softmax ----
        float mx0 = -1e30f, mx1 = -1e30f;
        #pragma unroll
        for (int nt = 0; nt < 8; nt++) {
            mx0 = fmaxf(mx0, fmaxf(sacc[nt][0], sacc[nt][1]));
            mx1 = fmaxf(mx1, fmaxf(sacc[nt][2], sacc[nt][3]));
        }
        mx0 = fmaxf(mx0, __shfl_xor_sync(0xffffffffu, mx0, 1));
        mx0 = fmaxf(mx0, __shfl_xor_sync(0xffffffffu, mx0, 2));
        mx1 = fmaxf(mx1, __shfl_xor_sync(0xffffffffu, mx1, 1));
        mx1 = fmaxf(mx1, __shfl_xor_sync(0xffffffffu, mx1, 2));

        float m0n = fmaxf(om[0], mx0);
        float m1n = fmaxf(om[1], mx1);
        float alpha0 = __expf(om[0] - m0n);
        float alpha1 = __expf(om[1] - m1n);

        float sum0 = 0.f, sum1 = 0.f;
        #pragma unroll
        for (int nt = 0; nt < 8; nt++) {
            float p0 = __expf(sacc[nt][0] - m0n);
            float p1 = __expf(sacc[nt][1] - m0n);
            float p2 = __expf(sacc[nt][2] - m1n);
            float p3 = __expf(sacc[nt][3] - m1n);
            sum0 += p0 + p1;
            sum1 += p2 + p3;
            *reinterpret_cast<float2*>(&Ps[row_lo * APAD + nt * 8 + 2 * c]) =
                make_float2(p0, p1);
            *reinterpret_cast<float2*>(&Ps[(row_lo + 8) * APAD + nt * 8 + 2 * c]) =
                make_float2(p2, p3);
        }
        sum0 += __shfl_xor_sync(0xffffffffu, sum0, 1);
        sum0 += __shfl_xor_sync(0xffffffffu, sum0, 2);
        sum1 += __shfl_xor_sync(0xffffffffu, sum1, 1);
        sum1 += __shfl_xor_sync(0xffffffffu, sum1, 2);

        ol[0] = ol[0] * alpha0 + sum0;
        ol[1] = ol[1] * alpha1 + sum1;
        om[0] = m0n;
        om[1] = m1n;

        #pragma unroll
        for (int nt = 0; nt < 8; nt++) {
            oacc[nt][0] *= alpha0;
            oacc[nt][1] *= alpha0;
            oacc[nt][2] *= alpha1;
            oacc[nt][3] *= alpha1;
        }
        __syncwarp();

        // ---- O += P @ V (3xTF32, transposed V planes) ----
        #pragma unroll
        for (int ks = 0; ks < 8; ks++) {
            const float* pb = Ps + row_lo * APAD + ks * 8;
            uint32_t ah[4], al[4];
            split_tf32(pb[c],                ah[0], al[0]);
            split_tf32(pb[8 * APAD + c],     ah[1], al[1]);
            split_tf32(pb[c + 4],            ah[2], al[2]);
            split_tf32(pb[8 * APAD + c + 4], ah[3], al[3]);
            #pragma unroll
            for (int nt = 0; nt < 8; nt++) {
                const int vidx = (nt * 8 + g) * APAD + ks * 8;
                uint32_t bh[2], bl[2];
                bh[0] = __float_as_uint(Vth[vidx + c]);
                bh[1] = __float_as_uint(Vth[vidx + c + 4]);
                bl[0] = __float_as_uint(Vtl[vidx + c]);
                bl[1] = __float_as_uint(Vtl[vidx + c + 4]);
                mma_tf32(oacc[nt], ah, bh);
                mma_tf32(oacc[nt], al, bh);
                mma_tf32(oacc[nt], ah, bl);
            }
        }
        __syncthreads();
    }

    // ---- epilogue ----
    const float inv0 = 1.f / ol[0];
    const float inv1 = 1.f / ol[1];
    const size_t base_lo = ((size_t)(b * LL + q_lo) * HH + h) * DD;
    const size_t base_hi = ((size_t)(b * LL + q_hi) * HH + h) * DD;
    #pragma unroll
    for (int nt = 0; nt < 8; nt++) {
        int d = nt * 8 + 2 * c;
        *reinterpret_cast<float2*>(&g_O[base_lo + d]) =
            make_float2(oacc[nt][0] * inv0, oacc[nt][1] * inv0);
        *reinterpret_cast<float2*>(&g_O[base_hi + d]) =
            make_float2(oacc[nt][2] * inv1, oacc[nt][3] * inv1);
    }
}

// ---------------------------------------------------------------------------
// Entry point
// ---------------------------------------------------------------------------
extern "C" void kernel_launch(void* const* d_in, const int* in_sizes, int n_in,
                              void* d_out, int out_size)
{
    const float* x    = (const float*)d_in[0];   // [B,L,E]
    const float* wqkv = (const float*)d_in[1];   // [3E,E]
    const float* bqkv = (const float*)d_in[2];   // [3E]
    const float* wout = (const float*)d_in[3];   // [E,E]
    const float* bout = (const float*)d_in[4];   // [E]
    float* out = (float*)d_out;                  // [B,L,E]

    (void)in_sizes; (void)n_in; (void)out_size;

    cudaFuncSetAttribute(tf32_gemm, cudaFuncAttributeMaxDynamicSharedMemorySize,
                         GEMM_SMEM);
    cudaFuncSetAttribute(attn_mma, cudaFuncAttributeMaxDynamicSharedMemorySize,
                         ATTN_SMEM);

    // QKV projection: M=8192, N=1536
    tf32_gemm<<<dim3(QKVN / 128, NTOK / 128), 256, GEMM_SMEM>>>(
        x, wqkv, bqkv, nullptr, 0);

    // banded attention
    attn_mma<<<dim3(LL / 64, HH, BB), 128, ATTN_SMEM>>>();

    // out projection: M=8192, N=512
    tf32_gemm<<<dim3(EE / 128, NTOK / 128), 256, GEMM_SMEM>>>(
        nullptr, wout, bout, out, 1);
}